// round 6
// baseline (speedup 1.0000x reference)
#include <cuda_runtime.h>
#include <cuda_bf16.h>
#include <math.h>

// Problem constants (GCNAggregator): B=4096, K=32, U=32768, V=100000, D=128
#define GCN_B 4096
#define GCN_K 32
#define GCN_U 32768
#define GCN_D 128

#define ROWS_PER_BLK 4          // block = ROWS_PER_BLK rows x 2 half-warps = 8 warps
#define AGG_THREADS (ROWS_PER_BLK * 2 * 32)

// Scratch (no cudaMalloc allowed)
__device__ int      g_col_deg[GCN_U];
__device__ unsigned g_row_mask[GCN_B];  // bit k set = k-th entry is first occurrence in its row

// ---------------------------------------------------------------------------
// Kernel 1: per-row dedupe (one warp per row) + column degree accumulation
// ---------------------------------------------------------------------------
__global__ void dedupe_degree_kernel(const int* __restrict__ neigh_cols) {
    int warp_in_block = threadIdx.x >> 5;
    int lane = threadIdx.x & 31;
    int b = blockIdx.x * (blockDim.x >> 5) + warp_in_block;

    int c = neigh_cols[b * GCN_K + lane];

    bool first = true;
    #pragma unroll
    for (int j = 0; j < GCN_K; j++) {
        int cj = __shfl_sync(0xFFFFFFFFu, c, j);
        if (j < lane && cj == c) first = false;
    }

    unsigned mask = __ballot_sync(0xFFFFFFFFu, first);
    if (lane == 0) g_row_mask[b] = mask;
    if (first) atomicAdd(&g_col_deg[c], 1);   // spread addresses -> cheap
}

// ---------------------------------------------------------------------------
// Volatile vectorized load: ordered w.r.t. other volatile loads, so ptxas
// cannot shrink the in-flight window below the rolling-buffer depth.
// ---------------------------------------------------------------------------
__device__ __forceinline__ float4 ldg_v4_pinned(const float4* p) {
    float4 v;
    asm volatile("ld.global.nc.v4.f32 {%0,%1,%2,%3}, [%4];"
                 : "=f"(v.x), "=f"(v.y), "=f"(v.z), "=f"(v.w)
                 : "l"(p));
    return v;
}

// ---------------------------------------------------------------------------
// Kernel 2: aggregation, split-K. Each row is handled by TWO warps (16
// gathers each); lane owns 4 consecutive dims (LDG.128). Rolling depth-8
// pinned pipeline. Partials combined through smem; half 0 stores.
// ---------------------------------------------------------------------------
__global__ void __launch_bounds__(AGG_THREADS)
aggregate_kernel(const int* __restrict__ neigh_cols,
                 const int* __restrict__ unique_ids,
                 const float4* __restrict__ embed_table4,  // [V, 32] float4
                 float4* __restrict__ out4) {              // [B, 32] float4
    const int warp = threadIdx.x >> 5;
    const int lane = threadIdx.x & 31;
    const int r    = warp >> 1;            // row within block, 0..ROWS_PER_BLK-1
    const int h    = warp & 1;             // half: gathers k in [16h, 16h+16)
    const int b    = blockIdx.x * ROWS_PER_BLK + r;

    __shared__ int2   s_wo[ROWS_PER_BLK][GCN_K];    // {off4, bitcast(w)}
    __shared__ float4 s_part[ROWS_PER_BLK][32];     // half-1 partial sums

    // ---- prologue: lane computes (off, w) for k = lane; warp h keeps only
    //      its own half (lanes 16h..16h+15) -> warp-private smem region ----
    const unsigned mask = g_row_mask[b];
    {
        int c = neigh_cols[b * GCN_K + lane];
        bool first = (mask >> lane) & 1u;
        float w = 0.0f;
        if (first) {
            int deg = __ldg(&g_col_deg[c]);         // >= 1 for first occurrences
            w = rsqrtf((float)deg);
        }
        w *= rsqrtf((float)__popc(mask));           // fold row scale in
        int off4 = __ldg(&unique_ids[c]) * (GCN_D / 4);
        if ((lane >> 4) == h)
            s_wo[r][lane] = make_int2(off4, __float_as_int(w));
    }
    __syncwarp();

    // ---- rolling depth-8 pinned gather over this warp's 16 neighbors ----
    constexpr int P = 8;
    const int kbase = h * 16;
    float4 buf[P];
    float  wb[P];
    #pragma unroll
    for (int i = 0; i < P; i++) {
        int2 t = s_wo[r][kbase + i];
        wb[i]  = __int_as_float(t.y);
        buf[i] = ldg_v4_pinned(embed_table4 + t.x + lane);
    }

    float4 acc = make_float4(0.f, 0.f, 0.f, 0.f);
    #pragma unroll
    for (int k = 0; k < 16; k++) {
        float4 v = buf[k & (P - 1)];
        float  w = wb[k & (P - 1)];
        acc.x = fmaf(w, v.x, acc.x);
        acc.y = fmaf(w, v.y, acc.y);
        acc.z = fmaf(w, v.z, acc.z);
        acc.w = fmaf(w, v.w, acc.w);
        if (k + P < 16) {
            int2 t = s_wo[r][kbase + k + P];
            wb[k & (P - 1)]  = __int_as_float(t.y);
            buf[k & (P - 1)] = ldg_v4_pinned(embed_table4 + t.x + lane);
        }
    }

    // ---- cross-warp reduce: half 1 publishes, half 0 combines + stores ----
    if (h == 1) s_part[r][lane] = acc;
    __syncthreads();
    if (h == 0) {
        float4 p = s_part[r][lane];
        acc.x += p.x; acc.y += p.y; acc.z += p.z; acc.w += p.w;
        out4[b * (GCN_D / 4) + lane] = acc;
    }
}

// ---------------------------------------------------------------------------
extern "C" void kernel_launch(void* const* d_in, const int* in_sizes, int n_in,
                              void* d_out, int out_size) {
    const int*    neigh_cols   = (const int*)d_in[0];
    const int*    unique_ids   = (const int*)d_in[1];
    const float4* embed_table4 = (const float4*)d_in[2];
    float4*       out4         = (float4*)d_out;

    // Zero column degrees via a graph memset node (no dedicated kernel launch).
    void* col_deg_ptr = nullptr;
    cudaGetSymbolAddress(&col_deg_ptr, g_col_deg);
    cudaMemsetAsync(col_deg_ptr, 0, GCN_U * sizeof(int));

    dedupe_degree_kernel<<<GCN_B / 8, 256>>>(neigh_cols);
    aggregate_kernel<<<GCN_B / ROWS_PER_BLK, AGG_THREADS>>>(
        neigh_cols, unique_ids, embed_table4, out4);
}